// round 8
// baseline (speedup 1.0000x reference)
#include <cuda_runtime.h>
#include <cstdint>

// ---------------------------------------------------------------------------
// Problem constants
// ---------------------------------------------------------------------------
#define B_       16
#define M_       100
#define NUM_CLS  80
#define HW_TOT   21824          // 128^2 + 64^2 + 32^2 + 16^2 + 8^2
#define NPIX     (B_ * HW_TOT)

#define CLS_N    (NPIX * 82)
#define REG_N    (NPIX * 6)
#define OFF_REG  ((size_t)CLS_N)
#define OFF_IND  (OFF_REG + REG_N)
#define OFF_NB   (OFF_IND + NPIX)

__device__ __constant__ int   c_off[5]   = {0, 16384, 20480, 21504, 21760};
__device__ __constant__ int   c_shift[5] = {7, 6, 5, 4, 3};
__device__ __constant__ float c_stride[5]= {8.f, 16.f, 32.f, 64.f, 128.f};

// ---------------------------------------------------------------------------
// Single fused kernel. grid=(23,16), block=256.
// Blocks 0-20: 1024-pixel single-level slabs (levels 0..2).
// Block 21: all of level 3 (256 px). Block 22: all of level 4 (64 px).
//   A: per-block candidate compaction (threads < M_).
//   B: 4 pixels/thread argmin -> smem records; coalesced ind write.
//   C: dense slab writes. cls via 2-row chunks (41 float4 = 164 floats):
//      pos20 = {s0,p0,0,0}, pos40 = {0,0,s1,p1}, rest zero. reg via aligned
//      smem->gmem float4 copy.
//   D: one-hot scatter (positives only), ordered after C by barrier.
// ---------------------------------------------------------------------------
__global__ __launch_bounds__(256) void fused_kernel(const float* __restrict__ gt,
                                                    float* __restrict__ out)
{
    __shared__ float4 cbnd[M_];
    __shared__ float4 cbox[M_];
    __shared__ float  carea[M_];
    __shared__ int    cj[M_];
    __shared__ int    clab[M_];
    __shared__ int    s_cnt;
    __shared__ alignas(16) float s_r6[1024 * 6];  // reg records, output layout
    __shared__ int    s_lab[1024];                // winner label or -1

    const int b  = blockIdx.y;
    const int bx = blockIdx.x;
    const int t  = threadIdx.x;

    int p0, npix, lev;
    if      (bx < 16) { p0 = bx * 1024; npix = 1024; lev = 0; }
    else if (bx < 20) { p0 = bx * 1024; npix = 1024; lev = 1; }
    else if (bx == 20){ p0 = 20480;     npix = 1024; lev = 2; }
    else if (bx == 21){ p0 = 21504;     npix = 256;  lev = 3; }
    else              { p0 = 21760;     npix = 64;   lev = 4; }

    const int   sh  = c_shift[lev];
    const int   fw  = 1 << sh;
    const float fS  = c_stride[lev];
    const float inv = 1.0f / fS;                 // exact (power of two)
    const int   off = c_off[lev];
    const int   g0  = b * HW_TOT + p0;

    const int local0 = p0 - off;
    const int by0 = local0 >> sh;
    const int by1 = (local0 + npix - 1) >> sh;

    if (t == 0) s_cnt = 0;
    __syncthreads();

    // ---- Phase A: candidate build ----
    int validp = 0;
    if (t < M_) {
        const float* bp = gt + (b * M_ + t) * 5;
        float x1 = bp[0], y1 = bp[1], x2 = bp[2], y2 = bp[3];

        float b0 = x1 * inv, b1 = y1 * inv, b2 = x2 * inv, b3 = y2 * inv;
        float cx = (b0 + b2) * 0.5f;
        float cy = (b1 + b3) * 0.5f;
        float hw = (b2 - b0) * 0.5f * 0.2f;
        float hh = (b3 - b1) * 0.5f * 0.2f;
        float px1 = fmaxf(floorf(cx - hw), 0.0f);
        float py1 = fmaxf(floorf(cy - hh), 0.0f);
        float px2 = fminf(ceilf(cx + hw), (float)fw);
        float py2 = fminf(ceilf(cy + hh), (float)fw);

        bool hit = (px2 > px1) && (py2 > py1) &&
                   (py1 <= (float)by1) && (py2 > (float)by0);
        if (hit) {
            int k = atomicAdd(&s_cnt, 1);
            cbnd[k]  = make_float4(px1, py1, px2, py2);
            cbox[k]  = make_float4(x1, y1, x2, y2);
            carea[k] = (x2 - x1) * (y2 - y1);
            cj[k]    = t;
            clab[k]  = (int)bp[4];
        }
        validp = (fabsf(x1) + fabsf(y1) + fabsf(x2) + fabsf(y2) > 0.0f) ? 1 : 0;
    }
    int nvalid = __syncthreads_count(validp);

    if (bx == 22 && t == 0)
        out[OFF_NB + b] = (float)nvalid;

    // ---- Phase B: 4 pixels per thread: argmin -> smem records, ind ----
    const int cnt = s_cnt;
    const float inv4 = 0.25f * inv;              // 1/(4*stride), exact
#pragma unroll
    for (int k = 0; k < 4; k++) {
        const int idx = k * 256 + t;
        if (idx >= npix) break;
        const int   p     = p0 + idx;
        const int   local = p - off;
        const int   y     = local >> sh;
        const int   x     = local & (fw - 1);
        const float fx    = (float)x;
        const float fy    = (float)y;

        float bestA = 1e7f;
        int   bestK = -1, bestJ = -1;
        for (int c = 0; c < cnt; c++) {
            float4 bb = cbnd[c];
            bool inside = (fx >= bb.x) & (fx < bb.z) & (fy >= bb.y) & (fy < bb.w);
            float a = carea[c];
            int   j = cj[c];
            if (inside && (a < bestA || (a == bestA && j < bestJ))) {
                bestA = a; bestJ = j; bestK = c;
            }
        }

        float soft = 1.0f, posf = 0.0f;
        float4 rg = make_float4(0.f, 0.f, 0.f, 0.f);
        int    lab = -1;
        if (bestK >= 0) {
            float4 wb = cbox[bestK];
            float sx = (fx + 0.5f) * fS;
            float sy = (fy + 0.5f) * fS;
            float l  = sx - wb.x;
            float tt = sy - wb.y;
            float r  = wb.z - sx;
            float bt = wb.w - sy;
            const float eps = 1e-6f;
            float q1 = fminf(fmaxf(fminf(l, r)  / fmaxf(fmaxf(l, r),  eps), 0.f), 1.f);
            float q2 = fminf(fmaxf(fminf(tt, bt)/ fmaxf(fmaxf(tt, bt), eps), 0.f), 1.f);
            soft = sqrtf(q1 * q2);
            posf = 1.0f;
            lab  = clab[bestK];
            rg = make_float4(l * inv4, tt * inv4, r * inv4, bt * inv4);
        }
        float* r6 = s_r6 + idx * 6;
        r6[0] = rg.x; r6[1] = rg.y; r6[2] = rg.z; r6[3] = rg.w;
        r6[4] = soft; r6[5] = posf;
        s_lab[idx] = lab;

        out[OFF_IND + g0 + idx] = (bestK >= 0) ? (float)bestJ : -1.0f;
    }
    __syncthreads();

    // ---- Phase C: dense slab writes ----
    // cls: stream of float4; per 2-row (164-float / 41-float4) chunk,
    // pos 20 = {soft0,posf0,0,0}, pos 40 = {0,0,soft1,posf1}, else zeros.
    {
        float4* cls4 = reinterpret_cast<float4*>(out + (size_t)g0 * 82);
        const int n4 = (npix * 82) >> 2;                 // npix/2 * 41
        for (int i = t; i < n4; i += 256) {
            unsigned q   = (unsigned)i / 41u;            // 2-row chunk
            int      pos = i - (int)q * 41;
            float4 v = make_float4(0.f, 0.f, 0.f, 0.f);
            if (pos == 20) {
                const float* r6 = s_r6 + (q * 2) * 6;
                v.x = r6[4]; v.y = r6[5];
            } else if (pos == 40) {
                const float* r6 = s_r6 + (q * 2 + 1) * 6;
                v.z = r6[4]; v.w = r6[5];
            }
            cls4[i] = v;
        }
    }
    // reg: smem layout == output layout -> aligned 16B copy
    {
        float4* reg4 = reinterpret_cast<float4*>(out + OFF_REG + (size_t)g0 * 6);
        const float4* sr4 = reinterpret_cast<const float4*>(s_r6);
        const int n4 = (npix * 6) >> 2;
        for (int i = t; i < n4; i += 256)
            reg4[i] = sr4[i];
    }
    __syncthreads();   // order dense cls stores before one-hot patches

    // ---- Phase D: one-hot scatter (positives only) ----
#pragma unroll
    for (int k = 0; k < 4; k++) {
        const int idx = k * 256 + t;
        if (idx >= npix) break;
        int lab = s_lab[idx];
        if (lab >= 0)
            out[(size_t)(g0 + idx) * 82 + lab] = 1.0f;
    }
}

// ---------------------------------------------------------------------------
extern "C" void kernel_launch(void* const* d_in, const int* in_sizes, int n_in,
                              void* d_out, int out_size)
{
    const float* gt  = (const float*)d_in[0];
    float*       out = (float*)d_out;

    dim3 grid(23, B_);                             // 368 blocks, single wave
    fused_kernel<<<grid, 256>>>(gt, out);
}

// round 9
// speedup vs baseline: 1.2881x; 1.2881x over previous
#include <cuda_runtime.h>
#include <cstdint>

// ---------------------------------------------------------------------------
// Problem constants
// ---------------------------------------------------------------------------
#define B_       16
#define M_       100
#define NUM_CLS  80
#define HW_TOT   21824          // 128^2 + 64^2 + 32^2 + 16^2 + 8^2
#define NPIX     (B_ * HW_TOT)

#define CLS_N    (NPIX * 82)
#define REG_N    (NPIX * 6)
#define OFF_REG  ((size_t)CLS_N)
#define OFF_IND  (OFF_REG + REG_N)
#define OFF_NB   (OFF_IND + NPIX)

__device__ __constant__ int   c_off[5]   = {0, 16384, 20480, 21504, 21760};
__device__ __constant__ int   c_shift[5] = {7, 6, 5, 4, 3};
__device__ __constant__ float c_stride[5]= {8.f, 16.f, 32.f, 64.f, 128.f};

// ---------------------------------------------------------------------------
// Single fused kernel. grid=(86,16), block=256, pinned to 8 blocks/SM.
//   A: per-block candidate compaction (threads < M_).
//   B: per-pixel argmin -> {soft,posf} into s_sp, label into s_lab;
//      reg written as 3x float2 (8B-aligned); coalesced ind write.
//   C: cls slab = zero float4 stream with {soft,posf} merged via the 2-row
//      chunk identity (41 float4 per 2 rows: pos20/pos40 carry soft/posf).
//   D: one-hot scatter (positives only), ordered after C by barrier.
// ---------------------------------------------------------------------------
__global__ __launch_bounds__(256, 8) void fused_kernel(const float* __restrict__ gt,
                                                       float* __restrict__ out)
{
    __shared__ float4 cbnd[M_];    // candidate shrunk bounds (level coords)
    __shared__ float4 cbox[M_];    // candidate image-space box
    __shared__ float  carea[M_];
    __shared__ int    cj[M_];      // original box index
    __shared__ int    clab[M_];
    __shared__ int    s_cnt;
    __shared__ float2 s_sp[256];   // per-pixel {soft, posf}
    __shared__ int    s_lab[256];  // winner label or -1

    const int b  = blockIdx.y;
    const int p0 = blockIdx.x * 256;
    const int t  = threadIdx.x;

    int lev;
    if      (p0 < 16384) lev = 0;
    else if (p0 < 20480) lev = 1;
    else if (p0 < 21504) lev = 2;
    else if (p0 < 21760) lev = 3;
    else                 lev = 4;

    const int   sh  = c_shift[lev];
    const int   fw  = 1 << sh;
    const float fS  = c_stride[lev];
    const float inv = 1.0f / fS;                 // exact (power of two)
    const int   off = c_off[lev];

    const int n_pix = min(256, HW_TOT - p0);     // 64 for last block, else 256
    const int g0    = b * HW_TOT + p0;

    const int local0 = p0 - off;
    const int by0 = local0 >> sh;
    const int by1 = (local0 + n_pix - 1) >> sh;

    if (t == 0) s_cnt = 0;
    __syncthreads();

    // ---- Phase A: candidate build ----
    int validp = 0;
    if (t < M_) {
        const float* bp = gt + (b * M_ + t) * 5;
        float x1 = bp[0], y1 = bp[1], x2 = bp[2], y2 = bp[3];

        float b0 = x1 * inv, b1 = y1 * inv, b2 = x2 * inv, b3 = y2 * inv;
        float cx = (b0 + b2) * 0.5f;
        float cy = (b1 + b3) * 0.5f;
        float hw = (b2 - b0) * 0.5f * 0.2f;
        float hh = (b3 - b1) * 0.5f * 0.2f;
        float px1 = fmaxf(floorf(cx - hw), 0.0f);
        float py1 = fmaxf(floorf(cy - hh), 0.0f);
        float px2 = fminf(ceilf(cx + hw), (float)fw);
        float py2 = fminf(ceilf(cy + hh), (float)fw);

        bool hit = (px2 > px1) && (py2 > py1) &&
                   (py1 <= (float)by1) && (py2 > (float)by0);
        if (hit) {
            int k = atomicAdd(&s_cnt, 1);
            cbnd[k]  = make_float4(px1, py1, px2, py2);
            cbox[k]  = make_float4(x1, y1, x2, y2);
            carea[k] = (x2 - x1) * (y2 - y1);
            cj[k]    = t;
            clab[k]  = (int)bp[4];
        }
        validp = (fabsf(x1) + fabsf(y1) + fabsf(x2) + fabsf(y2) > 0.0f) ? 1 : 0;
    }
    int nvalid = __syncthreads_count(validp);

    if (blockIdx.x == 85 && t == 0)
        out[OFF_NB + b] = (float)nvalid;

    // ---- Phase B: per-pixel argmin -> smem records, reg + ind writes ----
    if (t < n_pix) {
        const int   p     = p0 + t;
        const int   local = p - off;
        const int   y     = local >> sh;
        const int   x     = local & (fw - 1);
        const float fx    = (float)x;
        const float fy    = (float)y;

        const int cnt = s_cnt;
        float bestA = 1e7f;
        int   bestK = -1, bestJ = -1;
        for (int k = 0; k < cnt; k++) {
            float4 bb = cbnd[k];
            bool inside = (fx >= bb.x) & (fx < bb.z) & (fy >= bb.y) & (fy < bb.w);
            float a = carea[k];
            int   j = cj[k];
            if (inside && (a < bestA || (a == bestA && j < bestJ))) {
                bestA = a; bestJ = j; bestK = k;
            }
        }

        float soft = 1.0f, posf = 0.0f;
        float4 rg = make_float4(0.f, 0.f, 0.f, 0.f);
        int    lab = -1;
        if (bestK >= 0) {
            float4 wb = cbox[bestK];
            float sx = (fx + 0.5f) * fS;
            float sy = (fy + 0.5f) * fS;
            float l  = sx - wb.x;
            float tt = sy - wb.y;
            float r  = wb.z - sx;
            float bt = wb.w - sy;
            const float eps = 1e-6f;
            float q1 = fminf(fmaxf(fminf(l, r)  / fmaxf(fmaxf(l, r),  eps), 0.f), 1.f);
            float q2 = fminf(fmaxf(fminf(tt, bt)/ fmaxf(fmaxf(tt, bt), eps), 0.f), 1.f);
            soft = sqrtf(q1 * q2);
            posf = 1.0f;
            lab  = clab[bestK];
            float inv4 = 0.25f * inv;             // 1/(4*stride), exact
            rg = make_float4(l * inv4, tt * inv4, r * inv4, bt * inv4);
        }
        s_sp[t]  = make_float2(soft, posf);
        s_lab[t] = lab;

        const int g = g0 + t;
        float2* rp = reinterpret_cast<float2*>(out + OFF_REG + (size_t)g * 6);
        rp[0] = make_float2(rg.x, rg.y);
        rp[1] = make_float2(rg.z, rg.w);
        rp[2] = make_float2(soft, posf);

        out[OFF_IND + g] = (bestK >= 0) ? (float)bestJ : -1.0f;
    }
    __syncthreads();

    // ---- Phase C: cls slab as zero stream with {soft,posf} merged ----
    // 2 rows = 164 floats = 41 float4s. pos 20 = {s0,p0, r1c0=0, r1c1=0};
    // pos 40 = {0,0, s1,p1}. One-hot (cols < 80, incl. r1 cols 0,1 in pos20's
    // .z/.w slots) is patched in Phase D after the barrier.
    {
        float4* cls4 = reinterpret_cast<float4*>(out + (size_t)g0 * 82);
        const int n4 = (n_pix * 82) >> 2;                // n_pix/2 * 41
        for (int i = t; i < n4; i += 256) {
            unsigned q   = (unsigned)i / 41u;            // 2-row chunk index
            int      pos = i - (int)q * 41;
            float4 v = make_float4(0.f, 0.f, 0.f, 0.f);
            if (pos == 20) { float2 sp = s_sp[q * 2];     v.x = sp.x; v.y = sp.y; }
            if (pos == 40) { float2 sp = s_sp[q * 2 + 1]; v.z = sp.x; v.w = sp.y; }
            cls4[i] = v;
        }
    }
    __syncthreads();   // order dense cls stores before one-hot patches

    // ---- Phase D: one-hot scatter (positives only) ----
    if (t < n_pix) {
        int lab = s_lab[t];
        if (lab >= 0)
            out[(size_t)(g0 + t) * 82 + lab] = 1.0f;
    }
}

// ---------------------------------------------------------------------------
extern "C" void kernel_launch(void* const* d_in, const int* in_sizes, int n_in,
                              void* d_out, int out_size)
{
    const float* gt  = (const float*)d_in[0];
    float*       out = (float*)d_out;

    dim3 grid((HW_TOT + 255) / 256, B_);           // (86, 16)
    fused_kernel<<<grid, 256>>>(gt, out);
}